// round 3
// baseline (speedup 1.0000x reference)
#include <cuda_runtime.h>

#define NNN     129          // D + NA
#define THREADS 256
#define ROWS    64           // rows per block
#define KPT     16           // k-values per thread (4 threads per row)
#define SW      80           // padded weight row stride (floats), quarters at 0/20/40/60

// ---- persistent device scratch (allocation-free rule) ----
__device__ float        gPartI[256];
__device__ float        gPartN[256];
__device__ unsigned int gCount = 0;

__device__ __forceinline__ int pair_off(int i) {
    return NNN + i * (2 * NNN - i - 1) / 2;
}
__device__ __forceinline__ int koff(int k) {
    return (k >> 4) * 20 + (k & 15);
}

__device__ __forceinline__ unsigned long long pack2(float x) {
    unsigned long long r;
    asm("mov.b64 %0, {%1, %1};" : "=l"(r) : "f"(x));
    return r;
}
__device__ __forceinline__ void unpack2(unsigned long long v, float& a, float& b) {
    asm("mov.b64 {%0, %1}, %2;" : "=f"(a), "=f"(b) : "l"(v));
}
#define FMA2(acc, a, b) asm("fma.rn.f32x2 %0, %1, %2, %0;" : "+l"(acc) : "l"(a), "l"(b))

__device__ __forceinline__ float tanh_fast(float w) {
    float e, r;
    asm("ex2.approx.f32 %0, %1;" : "=f"(e) : "f"(w * 2.885390081777927f));
    asm("rcp.approx.f32 %0, %1;" : "=f"(r) : "f"(e + 1.0f));
    return fmaf(-2.0f, r, 1.0f);
}

// Shared layout (float offsets):
//  sWtT : [0, 5120)        64 x 80  (x-part of thresh_w^T, segmented quarters)
//  sG   : [5120, 15360)    128 x 80 (combined pair matrix, segmented quarters)
//  sWy  : [15360, 15424)
//  sB   : [15424, 15488)
//  swy  : [15488, 15552)
//  swys : [15552, 15616)
//  swlt : [15616, 15680)
//  sMisc: [15680, 15696)   [0]=wl[64], [1]=last-block flag
//  sRed : [15696, 15712)   8 warps x 2
#define SMEM_FLOATS 15712
#define SMEM_BYTES  (SMEM_FLOATS * 4)

__global__ void __launch_bounds__(THREADS, 2)
fused_kernel(const float* __restrict__ inps,
             const float* __restrict__ tw,
             const float* __restrict__ tb,
             const float* __restrict__ mw,
             float* __restrict__ out,
             int Bn) {
    extern __shared__ float sm[];
    float* sWtT  = sm;
    float* sG    = sm + 5120;
    float* sWy   = sm + 15360;
    float* sB    = sm + 15424;
    float* swy   = sm + 15488;
    float* swys  = sm + 15552;
    float* swlt  = sm + 15616;
    float* sMisc = sm + 15680;
    float* sRed  = sm + 15696;

    const int t    = threadIdx.x;
    const int q    = t & 3;                 // k-quarter
    const int r    = t >> 2;                // local row 0..63
    const int k0   = q * KPT;
    const int lane = t & 31;
    const int base = lane & ~3;             // partner-group base lane
    const int row0 = blockIdx.x * ROWS;

    // ---------------- weight prep ----------------
    for (int idx = t; idx < 64 * 64; idx += THREADS) {
        int k = idx >> 6, i = idx & 63;
        sWtT[i * SW + koff(k)] = tw[k * 65 + i];
    }
    for (int idx = t; idx < 64; idx += THREADS) {
        sWy[idx]  = tw[idx * 65 + 64];
        sB[idx]   = tb[idx];
        swy[idx]  = mw[pair_off(idx) + 63 - idx];
        swlt[idx] = mw[65 + idx];
        swys[idx] = mw[pair_off(64) + idx];
    }
    if (t == 0) sMisc[0] = mw[64];
    for (int idx = t; idx < 8192; idx += THREADS) {
        int i = idx >> 6, k = idx & 63;
        float v;
        if (i < 64) {
            v = mw[pair_off(i) + 64 + k - i];
        } else {
            int kp = i - 64;
            if (kp == k) v = 0.0f;
            else {
                int a = kp < k ? kp : k;
                int b = kp < k ? k : kp;
                int ia = 65 + a, jb = 65 + b;
                v = 0.5f * mw[pair_off(ia) + jb - ia - 1];
            }
        }
        sG[i * SW + koff(k)] = v;
    }

    // per-thread x quarter + y (registers, no smem staging)
    const float* rowp = inps + (long)(row0 + r) * 65;
    float xq[KPT];
#pragma unroll
    for (int j = 0; j < KPT; j++) xq[j] = __ldg(rowp + k0 + j);
    const float yv = __ldg(rowp + 64);

    __syncthreads();

    // ---------------- fused loop 1: i = 0..63 ----------------
    // c_k += x_i Wt[i][k];  g_k += x_i G[i][k]
    unsigned long long c[8], g[8];
#pragma unroll
    for (int j = 0; j < 8; j++) { c[j] = 0ULL; g[j] = 0ULL; }

#pragma unroll
    for (int ch = 0; ch < 4; ch++) {
#pragma unroll
        for (int j = 0; j < KPT; j++) {
            float xi = __shfl_sync(0xffffffffu, xq[j], base + ch);
            unsigned long long xp = pack2(xi);
            int i = ch * KPT + j;
            const ulonglong2* wA = reinterpret_cast<const ulonglong2*>(sWtT + i * SW + q * 20);
            const ulonglong2* wB = reinterpret_cast<const ulonglong2*>(sG   + i * SW + q * 20);
            ulonglong2 a0 = wA[0], a1 = wA[1], a2 = wA[2], a3 = wA[3];
            ulonglong2 b0 = wB[0], b1 = wB[1], b2 = wB[2], b3 = wB[3];
            FMA2(c[0], xp, a0.x); FMA2(c[1], xp, a0.y);
            FMA2(c[2], xp, a1.x); FMA2(c[3], xp, a1.y);
            FMA2(c[4], xp, a2.x); FMA2(c[5], xp, a2.y);
            FMA2(c[6], xp, a3.x); FMA2(c[7], xp, a3.y);
            FMA2(g[0], xp, b0.x); FMA2(g[1], xp, b0.y);
            FMA2(g[2], xp, b1.x); FMA2(g[3], xp, b1.y);
            FMA2(g[4], xp, b2.x); FMA2(g[5], xp, b2.y);
            FMA2(g[6], xp, b3.x); FMA2(g[7], xp, b3.y);
        }
    }

    // x . wy partial (this thread's quarter) — uses xq before it dies
    float accXW = 0.0f;
#pragma unroll
    for (int j = 0; j < KPT; j++) accXW = fmaf(xq[j], swy[k0 + j], accXW);

    // ---------------- tanh / penalties / small dots ----------------
    float d[KPT], s[KPT];
    float accDW = 0.0f, accSW = 0.0f, accI = 0.0f, accN = 0.0f;
#pragma unroll
    for (int j = 0; j < 8; j++) {
        float ca, cb;
        unpack2(c[j], ca, cb);
#pragma unroll
        for (int h = 0; h < 2; h++) {
            int   kk = 2 * j + h;
            int   k  = k0 + kk;
            float cv = (h == 0 ? ca : cb) + sB[k];
            float hv = yv * sWy[k];
            float w1s = cv + hv;
            float w2s = cv - hv;
            float t1 = tanh_fast(w1s);
            float t2 = tanh_fast(w2s);
            d[kk] = t1 - t2;
            s[kk] = t1 + t2;
            accDW = fmaf(d[kk], swlt[k], accDW);
            accSW = fmaf(s[kk], swys[k], accSW);
            float e1 = fmaf(-t1, t1, 1.0f);
            float e2 = fmaf(-t2, t2, 1.0f);
            accI = fmaf(e1, e1, accI);
            accI = fmaf(e2, e2, accI);
            float nt = fmaf(t2, w2s, -(t1 * w1s));
            accN = fmaf(nt, nt, accN);
        }
    }

    // ---------------- loop 2: i = 64..127 (s-half of G) ----------------
#pragma unroll
    for (int ch = 0; ch < 4; ch++) {
#pragma unroll
        for (int j = 0; j < KPT; j++) {
            float si = __shfl_sync(0xffffffffu, s[j], base + ch);
            unsigned long long sp = pack2(si);
            int i = 64 + ch * KPT + j;
            const ulonglong2* wB = reinterpret_cast<const ulonglong2*>(sG + i * SW + q * 20);
            ulonglong2 b0 = wB[0], b1 = wB[1], b2 = wB[2], b3 = wB[3];
            FMA2(g[0], sp, b0.x); FMA2(g[1], sp, b0.y);
            FMA2(g[2], sp, b1.x); FMA2(g[3], sp, b1.y);
            FMA2(g[4], sp, b2.x); FMA2(g[5], sp, b2.y);
            FMA2(g[6], sp, b3.x); FMA2(g[7], sp, b3.y);
        }
    }

    float gz = 0.0f;
#pragma unroll
    for (int j = 0; j < 8; j++) {
        float ga, gb;
        unpack2(g[j], ga, gb);
        gz = fmaf(d[2 * j],     ga, gz);
        gz = fmaf(d[2 * j + 1], gb, gz);
    }

    // ---------------- combine 4 partner lanes ----------------
    gz    += __shfl_xor_sync(0xffffffffu, gz, 1);
    gz    += __shfl_xor_sync(0xffffffffu, gz, 2);
    accDW += __shfl_xor_sync(0xffffffffu, accDW, 1);
    accDW += __shfl_xor_sync(0xffffffffu, accDW, 2);
    accSW += __shfl_xor_sync(0xffffffffu, accSW, 1);
    accSW += __shfl_xor_sync(0xffffffffu, accSW, 2);
    accXW += __shfl_xor_sync(0xffffffffu, accXW, 1);
    accXW += __shfl_xor_sync(0xffffffffu, accXW, 2);

    if (q == 0) {
        float diff = 1.0f
                   + 2.0f * yv * sMisc[0]
                   + accDW
                   + 2.0f * yv * accXW
                   + yv * accSW
                   + gz;
        out[row0 + r] = diff;
    }

    // ---------------- penalty reduction ----------------
#pragma unroll
    for (int off = 16; off > 0; off >>= 1) {
        accI += __shfl_xor_sync(0xffffffffu, accI, off);
        accN += __shfl_xor_sync(0xffffffffu, accN, off);
    }
    if (lane == 0) {
        sRed[t >> 5]     = accI;
        sRed[8 + (t >> 5)] = accN;
    }
    __syncthreads();
    if (t == 0) {
        float pI = 0.0f, pN = 0.0f;
#pragma unroll
        for (int w = 0; w < 8; w++) { pI += sRed[w]; pN += sRed[8 + w]; }
        gPartI[blockIdx.x] = pI;
        gPartN[blockIdx.x] = pN;
        __threadfence();
        unsigned int tk = atomicAdd(&gCount, 1u);
        sMisc[1] = (tk == gridDim.x - 1) ? 1.0f : 0.0f;
    }
    __syncthreads();

    if (sMisc[1] != 0.0f && t < 32) {
        __threadfence();
        double sI = 0.0, sN = 0.0;
        for (int i = t; i < (int)gridDim.x; i += 32) {
            sI += (double)gPartI[i];
            sN += (double)gPartN[i];
        }
#pragma unroll
        for (int off = 16; off > 0; off >>= 1) {
            sI += __shfl_xor_sync(0xffffffffu, sI, off);
            sN += __shfl_xor_sync(0xffffffffu, sN, off);
        }
        if (t == 0) {
            out[Bn]     = (float)(sI * (1.0 / 300.0));
            out[Bn + 1] = (float)sN;
            gCount = 0;   // reset for next graph replay
        }
    }
}

extern "C" void kernel_launch(void* const* d_in, const int* in_sizes, int n_in,
                              void* d_out, int out_size) {
    const float* inps = (const float*)d_in[0];
    const float* tw   = (const float*)d_in[1];
    const float* tb   = (const float*)d_in[2];
    const float* mw   = (const float*)d_in[3];
    float* out = (float*)d_out;

    int Bn = in_sizes[0] / 65;

    cudaFuncSetAttribute(fused_kernel,
                         cudaFuncAttributeMaxDynamicSharedMemorySize, SMEM_BYTES);

    fused_kernel<<<Bn / ROWS, THREADS, SMEM_BYTES>>>(inps, tw, tb, mw, out, Bn);
}